// round 5
// baseline (speedup 1.0000x reference)
#include <cuda_runtime.h>
#include <cuda_fp16.h>
#include <cuda_bf16.h>
#include <stdint.h>

// Problem shape (fixed by the reference)
#define BATCH 4
#define SEQ   2048
#define EMB   1024

// ---------------- scratch (device globals; no cudaMalloc allowed) ----------
__device__ __half d_Qh[(size_t)BATCH * SEQ * EMB];          // 16 MB
__device__ __half d_Kh[(size_t)BATCH * SEQ * EMB];          // 16 MB
__device__ __half d_Vt[(size_t)BATCH * SEQ * EMB];          // 16 MB  (V transposed: [B][E][S])
__device__ float  d_S [(size_t)BATCH * SEQ * SEQ];          // 64 MB  (scores)
__device__ __half d_P [(size_t)BATCH * SEQ * SEQ];          // 32 MB  (softmax probs)

// ---------------- fp32 -> fp16 convert -------------------------------------
__global__ void cvt_f32_f16(const float* __restrict__ in, __half* __restrict__ out, long n)
{
    long i = (long)blockIdx.x * blockDim.x + threadIdx.x;
    long stride = (long)gridDim.x * blockDim.x;
    for (long idx = i * 4; idx < n; idx += stride * 4) {
        float4 v = *reinterpret_cast<const float4*>(in + idx);
        __half2 h0 = __floats2half2_rn(v.x, v.y);
        __half2 h1 = __floats2half2_rn(v.z, v.w);
        *reinterpret_cast<__half2*>(out + idx)     = h0;
        *reinterpret_cast<__half2*>(out + idx + 2) = h1;
    }
}

// ---------------- V transpose + convert: V[B][S][E] -> Vt[B][E][S] ---------
__global__ void transpose_v(const float* __restrict__ V, __half* __restrict__ Vt)
{
    __shared__ float tile[32][33];
    int b  = blockIdx.z;
    int e0 = blockIdx.x * 32;
    int j0 = blockIdx.y * 32;
    const float* Vb  = V  + (size_t)b * SEQ * EMB;
    __half*      Vtb = Vt + (size_t)b * SEQ * EMB;
    for (int r = threadIdx.y; r < 32; r += 8)
        tile[r][threadIdx.x] = Vb[(size_t)(j0 + r) * EMB + e0 + threadIdx.x];
    __syncthreads();
    for (int r = threadIdx.y; r < 32; r += 8)
        Vtb[(size_t)(e0 + r) * SEQ + j0 + threadIdx.x] = __float2half_rn(tile[threadIdx.x][r]);
}

// ---------------- helpers ---------------------------------------------------
__device__ __forceinline__ uint32_t smem_u32(const void* p)
{
    uint32_t a;
    asm("{ .reg .u64 t; cvta.to.shared.u64 t, %1; cvt.u32.u64 %0, t; }" : "=r"(a) : "l"(p));
    return a;
}

__device__ __forceinline__ void cp_async16(uint32_t dst, const void* src)
{
    asm volatile("cp.async.cg.shared.global [%0], [%1], 16;" :: "r"(dst), "l"(src));
}
#define CP_COMMIT() asm volatile("cp.async.commit_group;" ::: "memory")
#define CP_WAIT(n)  asm volatile("cp.async.wait_group %0;" :: "n"(n) : "memory")

__device__ __forceinline__ void ldsm_x4_u(uint32_t& r0, uint32_t& r1, uint32_t& r2, uint32_t& r3,
                                          uint32_t sa)
{
    asm volatile("ldmatrix.sync.aligned.m8n8.x4.shared.b16 {%0,%1,%2,%3}, [%4];"
                 : "=r"(r0), "=r"(r1), "=r"(r2), "=r"(r3) : "r"(sa));
}

__device__ __forceinline__ void mma16816(float* d, const uint32_t* a, const uint32_t* b)
{
    asm("mma.sync.aligned.m16n8k16.row.col.f32.f16.f16.f32 "
        "{%0,%1,%2,%3}, {%4,%5,%6,%7}, {%8,%9}, {%0,%1,%2,%3};"
        : "+f"(d[0]), "+f"(d[1]), "+f"(d[2]), "+f"(d[3])
        : "r"(a[0]), "r"(a[1]), "r"(a[2]), "r"(a[3]), "r"(b[0]), "r"(b[1]));
}

// ---------------- TN GEMM: C[M,N] = alpha * A[M,K] @ B[N,K]^T ---------------
// fp16 in, fp32 accumulate. CTA tile 128x128x32, 4 warps (2x2),
// warp tile 64x64, mma.sync m16n8k16, 3-stage cp.async pipeline, 2 CTAs/SM.
#define BM 128
#define BN 128
#define BK 32
#define NSTG 3
#define ROWH   (BK + 8)                 // 40 halfs = 80 bytes per row
#define OP_BYT (BM * ROWH * 2)          // 10240 bytes per operand tile
#define STG_BYT (2 * OP_BYT)            // 20480 bytes per stage
#define GEMM_DSMEM (NSTG * STG_BYT)     // 61440 bytes

__global__ void __launch_bounds__(128, 2)
gemm_tn(const __half* __restrict__ A, const __half* __restrict__ B,
        float* __restrict__ C, int M, int N, int K, float alpha)
{
    extern __shared__ char dsm[];
    const uint32_t sbase = smem_u32(dsm);

    const int b = blockIdx.z;
    const __half* Ab = A + (size_t)b * M * K;
    const __half* Bb = B + (size_t)b * N * K;
    float*        Cb = C + (size_t)b * M * N;

    const int tm = blockIdx.y * BM;
    const int tn = blockIdx.x * BN;
    const int tid  = threadIdx.x;
    const int wid  = tid >> 5;
    const int lane = tid & 31;
    const int wm = (wid & 1) * 64;   // warp row offset within tile
    const int wn = (wid >> 1) * 64;  // warp col offset within tile

    // loader: 128 threads, 4 iters/operand; row = idx>>2, 16B chunk = idx&3
    const __half* Arow = Ab + (size_t)(tm + (tid >> 2)) * K + (tid & 3) * 8;
    const __half* Brow = Bb + (size_t)(tn + (tid >> 2)) * K + (tid & 3) * 8;
    const uint32_t dstA0 = sbase + (uint32_t)((tid >> 2) * 80 + (tid & 3) * 16);
    const uint32_t dstB0 = dstA0 + OP_BYT;

    float acc[4][8][4];
#pragma unroll
    for (int i = 0; i < 4; i++)
#pragma unroll
        for (int j = 0; j < 8; j++)
#pragma unroll
            for (int k = 0; k < 4; k++) acc[i][j][k] = 0.f;

    const int NC = K / BK;

    auto load_chunk = [&](int c, int s) {
        uint32_t so = (uint32_t)(s * STG_BYT);
        const __half* a0 = Arow + c * BK;
        const __half* b0 = Brow + c * BK;
#pragma unroll
        for (int r = 0; r < 4; ++r) {               // rows tid>>2 + 32*r
            cp_async16(dstA0 + so + (uint32_t)(r * 32 * 80), a0 + (size_t)(r * 32) * K);
            cp_async16(dstB0 + so + (uint32_t)(r * 32 * 80), b0 + (size_t)(r * 32) * K);
        }
    };

    // prologue: stages 0,1 in flight
    load_chunk(0, 0); CP_COMMIT();
    load_chunk(1, 1); CP_COMMIT();

    // per-thread ldmatrix base offsets (within a stage)
    const uint32_t lA = sbase + (uint32_t)((wm + (lane & 15)) * 80 + ((lane >> 4) << 4));
    const uint32_t lB = sbase + OP_BYT + (uint32_t)((wn + (lane & 15)) * 80 + ((lane >> 4) << 4));

    for (int c = 0; c < NC; ++c) {
        if (c + 1 < NC) { CP_WAIT(1); } else { CP_WAIT(0); }
        __syncthreads();
        if (c + 2 < NC) { load_chunk(c + 2, (c + 2) % NSTG); CP_COMMIT(); }

        const uint32_t so = (uint32_t)((c % NSTG) * STG_BYT);

#pragma unroll
        for (int kk = 0; kk < BK; kk += 16) {
            uint32_t af[4][4];
            uint32_t bf[8][2];
#pragma unroll
            for (int mt = 0; mt < 4; ++mt)
                ldsm_x4_u(af[mt][0], af[mt][1], af[mt][2], af[mt][3],
                          lA + so + (uint32_t)(mt * 16 * 80 + kk * 2));
#pragma unroll
            for (int nb = 0; nb < 4; ++nb) {
                uint32_t r0, r1, r2, r3;
                ldsm_x4_u(r0, r1, r2, r3, lB + so + (uint32_t)(nb * 16 * 80 + kk * 2));
                // r0=n[0:8)k[0:8) r1=n[8:16)k[0:8) r2=n[0:8)k[8:16) r3=n[8:16)k[8:16)
                bf[nb * 2 + 0][0] = r0; bf[nb * 2 + 0][1] = r2;
                bf[nb * 2 + 1][0] = r1; bf[nb * 2 + 1][1] = r3;
            }
#pragma unroll
            for (int mt = 0; mt < 4; ++mt)
#pragma unroll
                for (int nt = 0; nt < 8; ++nt)
                    mma16816(acc[mt][nt], af[mt], bf[nt]);
        }
    }

    // epilogue
#pragma unroll
    for (int mt = 0; mt < 4; ++mt) {
#pragma unroll
        for (int nt = 0; nt < 8; ++nt) {
            int r = tm + wm + mt * 16 + (lane >> 2);
            int c = tn + wn + nt * 8 + ((lane & 3) << 1);
            float2 v0 = make_float2(acc[mt][nt][0] * alpha, acc[mt][nt][1] * alpha);
            float2 v1 = make_float2(acc[mt][nt][2] * alpha, acc[mt][nt][3] * alpha);
            *reinterpret_cast<float2*>(&Cb[(size_t)r * N + c])       = v0;
            *reinterpret_cast<float2*>(&Cb[(size_t)(r + 8) * N + c]) = v1;
        }
    }
}

// ---------------- row softmax (+ mask): S fp32 -> P fp16 --------------------
__device__ __forceinline__ float warp_max(float v)
{
#pragma unroll
    for (int o = 16; o > 0; o >>= 1) v = fmaxf(v, __shfl_xor_sync(0xffffffffu, v, o));
    return v;
}
__device__ __forceinline__ float warp_sum(float v)
{
#pragma unroll
    for (int o = 16; o > 0; o >>= 1) v += __shfl_xor_sync(0xffffffffu, v, o);
    return v;
}

__global__ void __launch_bounds__(256)
softmax_kernel(const float* __restrict__ S, const float* __restrict__ mask,
               __half* __restrict__ P)
{
    __shared__ float red[8];
    int row = blockIdx.x;                 // b*SEQ + i
    const float* s = S    + (size_t)row * SEQ;
    const float* m = mask + (size_t)row * SEQ;
    __half*      p = P    + (size_t)row * SEQ;

    int base = threadIdx.x * 8;
    float v[8];
    {
        float4 a  = *reinterpret_cast<const float4*>(s + base);
        float4 b4 = *reinterpret_cast<const float4*>(s + base + 4);
        float4 ma = *reinterpret_cast<const float4*>(m + base);
        float4 mb = *reinterpret_cast<const float4*>(m + base + 4);
        v[0] = a.x  + ma.x; v[1] = a.y  + ma.y; v[2] = a.z  + ma.z; v[3] = a.w  + ma.w;
        v[4] = b4.x + mb.x; v[5] = b4.y + mb.y; v[6] = b4.z + mb.z; v[7] = b4.w + mb.w;
    }
    float mx = v[0];
#pragma unroll
    for (int i = 1; i < 8; i++) mx = fmaxf(mx, v[i]);
    mx = warp_max(mx);
    int wid = threadIdx.x >> 5, lane = threadIdx.x & 31;
    if (lane == 0) red[wid] = mx;
    __syncthreads();
    if (wid == 0) {
        float t = (lane < 8) ? red[lane] : -1e30f;
        t = warp_max(t);
        if (lane == 0) red[0] = t;
    }
    __syncthreads();
    mx = red[0];

    float sum = 0.f;
#pragma unroll
    for (int i = 0; i < 8; i++) { v[i] = __expf(v[i] - mx); sum += v[i]; }
    sum = warp_sum(sum);
    __syncthreads();
    if (lane == 0) red[wid] = sum;
    __syncthreads();
    if (wid == 0) {
        float t = (lane < 8) ? red[lane] : 0.f;
        t = warp_sum(t);
        if (lane == 0) red[0] = t;
    }
    __syncthreads();
    float inv = 1.0f / red[0];

    __half h[8];
#pragma unroll
    for (int i = 0; i < 8; i++) h[i] = __float2half_rn(v[i] * inv);
    *reinterpret_cast<uint4*>(p + base) = *reinterpret_cast<const uint4*>(h);
}

// ---------------- launch -----------------------------------------------------
extern "C" void kernel_launch(void* const* d_in, const int* in_sizes, int n_in,
                              void* d_out, int out_size)
{
    const float* Q    = (const float*)d_in[0];
    const float* K    = (const float*)d_in[1];
    const float* V    = (const float*)d_in[2];
    const float* mask = (const float*)d_in[3];
    float* out = (float*)d_out;

    void *pQh, *pKh, *pVt, *pS, *pP;
    cudaGetSymbolAddress(&pQh, d_Qh);
    cudaGetSymbolAddress(&pKh, d_Kh);
    cudaGetSymbolAddress(&pVt, d_Vt);
    cudaGetSymbolAddress(&pS,  d_S);
    cudaGetSymbolAddress(&pP,  d_P);

    cudaFuncSetAttribute(gemm_tn, cudaFuncAttributeMaxDynamicSharedMemorySize, GEMM_DSMEM);

    const long nQK = (long)BATCH * SEQ * EMB;

    cvt_f32_f16<<<4096, 256>>>(Q, (__half*)pQh, nQK);
    cvt_f32_f16<<<4096, 256>>>(K, (__half*)pKh, nQK);
    transpose_v<<<dim3(EMB / 32, SEQ / 32, BATCH), dim3(32, 8)>>>(V, (__half*)pVt);

    // S = (1/sqrt(E)) * Q @ K^T ; 1/sqrt(1024) == 0.03125 exactly
    gemm_tn<<<dim3(SEQ / BN, SEQ / BM, BATCH), 128, GEMM_DSMEM>>>(
        (const __half*)pQh, (const __half*)pKh, (float*)pS,
        SEQ, SEQ, EMB, 0.03125f);

    softmax_kernel<<<BATCH * SEQ, 256>>>((const float*)pS, mask, (__half*)pP);

    // O = P @ V  (V stored transposed, so TN form again)
    gemm_tn<<<dim3(EMB / BN, SEQ / BM, BATCH), 128, GEMM_DSMEM>>>(
        (const __half*)pP, (const __half*)pVt, out,
        SEQ, EMB, SEQ, 1.0f);
}

// round 6
// speedup vs baseline: 1.0175x; 1.0175x over previous
#include <cuda_runtime.h>
#include <cuda_fp16.h>
#include <cuda_bf16.h>
#include <stdint.h>

// Problem shape (fixed by the reference)
#define BATCH 4
#define SEQ   2048
#define EMB   1024

// ---------------- scratch (device globals; no cudaMalloc allowed) ----------
__device__ __half d_Qh[(size_t)BATCH * SEQ * EMB];           // 16 MB (Q * 1/32, fp16)
__device__ __half d_Kh[(size_t)BATCH * SEQ * EMB];           // 16 MB
__device__ __half d_Vt[(size_t)BATCH * SEQ * EMB];           // 16 MB (V transposed: [B][E][S])
__device__ __half d_E [(size_t)BATCH * SEQ * SEQ];           // 32 MB (exp(scores+mask), fp16)
__device__ float  d_RS[(size_t)16 * BATCH * SEQ];            // 512 KB partial row sums

// ---------------- fp32 -> fp16 convert (with scale) -------------------------
__global__ void cvt_f32_f16(const float* __restrict__ in, __half* __restrict__ out,
                            long n, float scale)
{
    long i = (long)blockIdx.x * blockDim.x + threadIdx.x;
    long stride = (long)gridDim.x * blockDim.x;
    for (long idx = i * 4; idx < n; idx += stride * 4) {
        float4 v = *reinterpret_cast<const float4*>(in + idx);
        __half2 h0 = __floats2half2_rn(v.x * scale, v.y * scale);
        __half2 h1 = __floats2half2_rn(v.z * scale, v.w * scale);
        *reinterpret_cast<__half2*>(out + idx)     = h0;
        *reinterpret_cast<__half2*>(out + idx + 2) = h1;
    }
}

// ---------------- V transpose + convert: V[B][S][E] -> Vt[B][E][S] ---------
__global__ void transpose_v(const float* __restrict__ V, __half* __restrict__ Vt)
{
    __shared__ float tile[32][33];
    int b  = blockIdx.z;
    int e0 = blockIdx.x * 32;
    int j0 = blockIdx.y * 32;
    const float* Vb  = V  + (size_t)b * SEQ * EMB;
    __half*      Vtb = Vt + (size_t)b * SEQ * EMB;
    for (int r = threadIdx.y; r < 32; r += 8)
        tile[r][threadIdx.x] = Vb[(size_t)(j0 + r) * EMB + e0 + threadIdx.x];
    __syncthreads();
    for (int r = threadIdx.y; r < 32; r += 8)
        Vtb[(size_t)(e0 + r) * SEQ + j0 + threadIdx.x] = __float2half_rn(tile[threadIdx.x][r]);
}

// ---------------- shared GEMM machinery (proven R2 core) --------------------
#define BM 128
#define BN 128
#define BKT 64

__device__ __forceinline__ void ldsm_x4(uint32_t& r0, uint32_t& r1, uint32_t& r2, uint32_t& r3,
                                        const __half* p)
{
    uint32_t sa = (uint32_t)__cvta_generic_to_shared(p);
    asm volatile("ldmatrix.sync.aligned.m8n8.x4.shared.b16 {%0,%1,%2,%3}, [%4];"
                 : "=r"(r0), "=r"(r1), "=r"(r2), "=r"(r3) : "r"(sa));
}

__device__ __forceinline__ void mma16816(float* d, const uint32_t* a, const uint32_t* b)
{
    asm("mma.sync.aligned.m16n8k16.row.col.f32.f16.f16.f32 "
        "{%0,%1,%2,%3}, {%4,%5,%6,%7}, {%8,%9}, {%0,%1,%2,%3};"
        : "+f"(d[0]), "+f"(d[1]), "+f"(d[2]), "+f"(d[3])
        : "r"(a[0]), "r"(a[1]), "r"(a[2]), "r"(a[3]), "r"(b[0]), "r"(b[1]));
}

// Main-loop body shared by both GEMMs (K-contiguous TN, 128x128 tile, 8 warps)
#define GEMM_MAINLOOP(Ab, Bb, Kdim)                                                       \
    for (int k0 = 0; k0 < (Kdim); k0 += BKT) {                                            \
        _Pragma("unroll")                                                                 \
        for (int it = 0; it < 4; ++it) {                                                  \
            int idx = tid + it * 256;                                                     \
            int row = idx >> 3;                                                           \
            int col = (idx & 7) * 8;                                                      \
            *reinterpret_cast<uint4*>(&As[row][col]) =                                    \
                *reinterpret_cast<const uint4*>(&(Ab)[(size_t)(tm + row) * (Kdim) + k0 + col]); \
            *reinterpret_cast<uint4*>(&Bs[row][col]) =                                    \
                *reinterpret_cast<const uint4*>(&(Bb)[(size_t)(tn + row) * (Kdim) + k0 + col]); \
        }                                                                                 \
        __syncthreads();                                                                  \
        _Pragma("unroll")                                                                 \
        for (int kk = 0; kk < BKT; kk += 16) {                                            \
            uint32_t af[4][4];                                                            \
            uint32_t bf[4][2];                                                            \
            _Pragma("unroll")                                                             \
            for (int mt = 0; mt < 4; ++mt) {                                              \
                const __half* p = &As[wm + mt * 16 + (lane & 15)][kk + ((lane >> 4) << 3)]; \
                ldsm_x4(af[mt][0], af[mt][1], af[mt][2], af[mt][3], p);                   \
            }                                                                             \
            _Pragma("unroll")                                                             \
            for (int nb = 0; nb < 2; ++nb) {                                              \
                uint32_t r0, r1, r2, r3;                                                  \
                const __half* p = &Bs[wn + nb * 16 + (lane & 15)][kk + ((lane >> 4) << 3)]; \
                ldsm_x4(r0, r1, r2, r3, p);                                               \
                bf[nb * 2 + 0][0] = r0; bf[nb * 2 + 0][1] = r2;                           \
                bf[nb * 2 + 1][0] = r1; bf[nb * 2 + 1][1] = r3;                           \
            }                                                                             \
            _Pragma("unroll")                                                             \
            for (int mt = 0; mt < 4; ++mt)                                                \
                _Pragma("unroll")                                                         \
                for (int nt = 0; nt < 4; ++nt)                                            \
                    mma16816(acc[mt][nt], af[mt], bf[nt]);                                \
        }                                                                                 \
        __syncthreads();                                                                  \
    }

// ---------------- GEMM1: E = exp(Q*K^T + mask), partial row sums ------------
__global__ void __launch_bounds__(256, 2)
gemm_exp(const __half* __restrict__ A, const __half* __restrict__ B,
         const float* __restrict__ mask, __half* __restrict__ E,
         float* __restrict__ RSpart)
{
    __shared__ __half As[BM][BKT + 8];
    __shared__ __half Bs[BN][BKT + 8];
    __shared__ float rowpart[4][BM];

    const int b = blockIdx.z;
    const __half* Ab = A + (size_t)b * SEQ * EMB;
    const __half* Bb = B + (size_t)b * SEQ * EMB;

    const int tm = blockIdx.y * BM;
    const int tn = blockIdx.x * BN;
    const int tid  = threadIdx.x;
    const int wid  = tid >> 5;
    const int lane = tid & 31;
    const int wm = (wid & 1) * 64;
    const int wn = (wid >> 1) * 32;

    float acc[4][4][4];
#pragma unroll
    for (int i = 0; i < 4; i++)
#pragma unroll
        for (int j = 0; j < 4; j++)
#pragma unroll
            for (int k = 0; k < 4; k++) acc[i][j][k] = 0.f;

    GEMM_MAINLOOP(Ab, Bb, EMB)

    // --- epilogue: mask add, exp, fp16 store, row-sum partials ---
    const float* mb = mask + (size_t)b * SEQ * SEQ;
    __half*      Eb = E    + (size_t)b * SEQ * SEQ;

#pragma unroll
    for (int mt = 0; mt < 4; ++mt) {
        int r  = tm + wm + mt * 16 + (lane >> 2);
        float sum0 = 0.f, sum1 = 0.f;
#pragma unroll
        for (int nt = 0; nt < 4; ++nt) {
            int c = tn + wn + nt * 8 + ((lane & 3) << 1);
            float2 m0 = *reinterpret_cast<const float2*>(&mb[(size_t)r * SEQ + c]);
            float2 m1 = *reinterpret_cast<const float2*>(&mb[(size_t)(r + 8) * SEQ + c]);
            float e00 = __expf(acc[mt][nt][0] + m0.x);
            float e01 = __expf(acc[mt][nt][1] + m0.y);
            float e10 = __expf(acc[mt][nt][2] + m1.x);
            float e11 = __expf(acc[mt][nt][3] + m1.y);
            *reinterpret_cast<__half2*>(&Eb[(size_t)r * SEQ + c])       = __floats2half2_rn(e00, e01);
            *reinterpret_cast<__half2*>(&Eb[(size_t)(r + 8) * SEQ + c]) = __floats2half2_rn(e10, e11);
            sum0 += e00 + e01;
            sum1 += e10 + e11;
        }
        // quad reduce (lanes with same lane>>2 share the row)
        sum0 += __shfl_xor_sync(0xffffffffu, sum0, 1);
        sum0 += __shfl_xor_sync(0xffffffffu, sum0, 2);
        sum1 += __shfl_xor_sync(0xffffffffu, sum1, 1);
        sum1 += __shfl_xor_sync(0xffffffffu, sum1, 2);
        if ((lane & 3) == 0) {
            int rl = wm + mt * 16 + (lane >> 2);
            rowpart[wid >> 1][rl]     = sum0;
            rowpart[wid >> 1][rl + 8] = sum1;
        }
    }
    __syncthreads();
    if (tid < BM) {
        float rs = rowpart[0][tid] + rowpart[1][tid] + rowpart[2][tid] + rowpart[3][tid];
        RSpart[(size_t)blockIdx.x * (BATCH * SEQ) + (size_t)b * SEQ + tm + tid] = rs;
    }
}

// ---------------- GEMM2: O = (E @ Vt^T) / rowsum -----------------------------
__global__ void __launch_bounds__(256, 2)
gemm_out(const __half* __restrict__ A, const __half* __restrict__ B,
         float* __restrict__ C, const float* __restrict__ RSpart)
{
    __shared__ __half As[BM][BKT + 8];
    __shared__ __half Bs[BN][BKT + 8];
    __shared__ float inv[BM];

    const int b = blockIdx.z;
    const __half* Ab = A + (size_t)b * SEQ * SEQ;   // E: [q][k], K = SEQ
    const __half* Bb = B + (size_t)b * SEQ * EMB;   // Vt: [e][s], K = SEQ
    float*        Cb = C + (size_t)b * SEQ * EMB;   // out: [q][e], N = EMB

    const int tm = blockIdx.y * BM;
    const int tn = blockIdx.x * BN;
    const int tid  = threadIdx.x;
    const int wid  = tid >> 5;
    const int lane = tid & 31;
    const int wm = (wid & 1) * 64;
    const int wn = (wid >> 1) * 32;

    // reciprocal row sums (16 partials per row)
    if (tid < BM) {
        float rs = 0.f;
#pragma unroll
        for (int i = 0; i < 16; ++i)
            rs += RSpart[(size_t)i * (BATCH * SEQ) + (size_t)b * SEQ + tm + tid];
        inv[tid] = 1.0f / rs;
    }

    float acc[4][4][4];
#pragma unroll
    for (int i = 0; i < 4; i++)
#pragma unroll
        for (int j = 0; j < 4; j++)
#pragma unroll
            for (int k = 0; k < 4; k++) acc[i][j][k] = 0.f;

    GEMM_MAINLOOP(Ab, Bb, SEQ)

    // epilogue: normalize and store fp32
#pragma unroll
    for (int mt = 0; mt < 4; ++mt) {
        int rl = wm + mt * 16 + (lane >> 2);
        float i0 = inv[rl];
        float i1 = inv[rl + 8];
        int r = tm + rl;
#pragma unroll
        for (int nt = 0; nt < 4; ++nt) {
            int c = tn + wn + nt * 8 + ((lane & 3) << 1);
            float2 v0 = make_float2(acc[mt][nt][0] * i0, acc[mt][nt][1] * i0);
            float2 v1 = make_float2(acc[mt][nt][2] * i1, acc[mt][nt][3] * i1);
            *reinterpret_cast<float2*>(&Cb[(size_t)r * EMB + c])       = v0;
            *reinterpret_cast<float2*>(&Cb[(size_t)(r + 8) * EMB + c]) = v1;
        }
    }
}

// ---------------- launch -----------------------------------------------------
extern "C" void kernel_launch(void* const* d_in, const int* in_sizes, int n_in,
                              void* d_out, int out_size)
{
    const float* Q    = (const float*)d_in[0];
    const float* K    = (const float*)d_in[1];
    const float* V    = (const float*)d_in[2];
    const float* mask = (const float*)d_in[3];
    float* out = (float*)d_out;

    void *pQh, *pKh, *pVt, *pE, *pRS;
    cudaGetSymbolAddress(&pQh, d_Qh);
    cudaGetSymbolAddress(&pKh, d_Kh);
    cudaGetSymbolAddress(&pVt, d_Vt);
    cudaGetSymbolAddress(&pE,  d_E);
    cudaGetSymbolAddress(&pRS, d_RS);

    const long nQK = (long)BATCH * SEQ * EMB;

    // Q scaled by 1/sqrt(EMB) = 1/32 exactly
    cvt_f32_f16<<<4096, 256>>>(Q, (__half*)pQh, nQK, 0.03125f);
    cvt_f32_f16<<<4096, 256>>>(K, (__half*)pKh, nQK, 1.0f);
    transpose_v<<<dim3(EMB / 32, SEQ / 32, BATCH), dim3(32, 8)>>>(V, (__half*)pVt);

    // E = exp(Q K^T / 32 + mask), partial row sums
    gemm_exp<<<dim3(SEQ / BN, SEQ / BM, BATCH), 256>>>(
        (const __half*)pQh, (const __half*)pKh, mask,
        (__half*)pE, (float*)pRS);

    // O = (E @ V) / rowsum
    gemm_out<<<dim3(EMB / BN, SEQ / BM, BATCH), 256>>>(
        (const __half*)pE, (const __half*)pVt, out, (const float*)pRS);
}